// round 15
// baseline (speedup 1.0000x reference)
#include <cuda_runtime.h>
#include <cuda_fp16.h>
#include <cuda_bf16.h>
#include <stdint.h>

#define N_NODES   10000
#define NPAD      10112    // 79 * 128, zero-padded rows for M tiles
#define ROW_WORDS 320
#define USED_WORDS 313
#define D         256
#define DW        128      // D in b32 words (2 bf16 each)
#define E_EDGES   320000
#define CAP       2048
#define SROW      264      // B smem row: 256 interleaved words + 8 pad

// ---- scratch (__device__ globals; no allocations allowed) ----
__device__ unsigned g_bits[N_NODES * ROW_WORDS];
__device__ float    g_dinv[N_NODES];
__device__ __half   g_zh[N_NODES * D];               // z = x @ W (UNscaled), fp16
__device__ __align__(16) unsigned g_xh[NPAD * DW];   // x hi split, bf16x2 packed
__device__ __align__(16) unsigned g_xl[NPAD * DW];   // x lo split
__device__ __align__(16) unsigned g_wth[D * DW];     // W^T hi split [n][k]
__device__ __align__(16) unsigned g_wtl[D * DW];     // W^T lo split

// ============================ setup kernels ================================
__global__ void zero_bits_kernel() {
    int idx    = blockIdx.x * blockDim.x + threadIdx.x;
    int stride = gridDim.x * blockDim.x;
    uint4 zz = make_uint4(0u, 0u, 0u, 0u);
    uint4* p = reinterpret_cast<uint4*>(g_bits);
    for (int i = idx; i < N_NODES * ROW_WORDS / 4; i += stride) p[i] = zz;
}

__global__ void edge_kernel(const int* __restrict__ ei) {
    int e = blockIdx.x * blockDim.x + threadIdx.x;
    if (e >= E_EDGES) return;
    int s = ei[e];
    int d = ei[E_EDGES + e];
    if ((unsigned)s >= N_NODES || (unsigned)d >= N_NODES) return;
    atomicOr(&g_bits[s * ROW_WORDS + (d >> 5)], 1u << (d & 31));
    atomicOr(&g_bits[d * ROW_WORDS + (s >> 5)], 1u << (s & 31));
}

__global__ void degree_kernel() {
    int warp = (blockIdx.x * blockDim.x + threadIdx.x) >> 5;
    int lane = threadIdx.x & 31;
    if (warp >= N_NODES) return;
    const unsigned* row = &g_bits[warp * ROW_WORDS];
    int cnt = 0;
    for (int w = lane; w < USED_WORDS; w += 32) cnt += __popc(row[w]);
    #pragma unroll
    for (int off = 16; off; off >>= 1) cnt += __shfl_down_sync(0xffffffffu, cnt, off);
    if (lane == 0) g_dinv[warp] = rsqrtf((float)(cnt + 1));
}

__device__ __forceinline__ unsigned pack_bf16(float a, float b) {
    return (unsigned)__bfloat16_as_ushort(__float2bfloat16(a)) |
           ((unsigned)__bfloat16_as_ushort(__float2bfloat16(b)) << 16);
}

__global__ void split_x_kernel(const float* __restrict__ X) {
    int idx = blockIdx.x * blockDim.x + threadIdx.x;   // over NPAD*DW
    if (idx >= NPAD * DW) return;
    int m = idx >> 7, w = idx & 127;
    float v0 = 0.f, v1 = 0.f;
    if (m < N_NODES) { v0 = X[m * D + 2 * w]; v1 = X[m * D + 2 * w + 1]; }
    float h0 = __bfloat162float(__float2bfloat16(v0));
    float h1 = __bfloat162float(__float2bfloat16(v1));
    g_xh[idx] = pack_bf16(v0, v1);
    g_xl[idx] = pack_bf16(v0 - h0, v1 - h1);
}

__global__ void split_w_kernel(const float* __restrict__ W) {
    int idx = blockIdx.x * blockDim.x + threadIdx.x;   // over D*DW
    if (idx >= D * DW) return;
    int n = idx >> 7, w = idx & 127;
    float v0 = W[(2 * w) * D + n], v1 = W[(2 * w + 1) * D + n];
    float h0 = __bfloat162float(__float2bfloat16(v0));
    float h1 = __bfloat162float(__float2bfloat16(v1));
    g_wth[idx] = pack_bf16(v0, v1);
    g_wtl[idx] = pack_bf16(v0 - h0, v1 - h1);
}

// ================= mma.sync GEMM: g_zh = fp16(x @ W) =======================
// Grid (D/64, NPAD/128): blockIdx.x = N tile (4), blockIdx.y = M tile (79).
// Block 256 thr (8 warps): tile 128(M) x 64(N), full K=256 resident in smem.
// Warp w owns rows [16w, 16w+16). 3-mma bf16 split: Ah*Bh + Al*Bh + Ah*Bl.
// A fragments double-buffered in registers (prefetch next ks during mma).
__global__ __launch_bounds__(256) void gemm_mma_kernel() {
    extern __shared__ __align__(16) unsigned sw[];   // 64 * SROW words

    int tid  = threadIdx.x;
    int wid  = tid >> 5;
    int lane = tid & 31;
    int grp  = lane >> 2;     // 0..7
    int ctg  = lane & 3;      // 0..3
    int bm   = blockIdx.y * 128;
    int bn   = blockIdx.x * 64;

    // ---- fill B smem: (hi,lo) word-interleaved per kw, row pad +8 ----
    {
        int nl  = tid >> 2;          // 0..63 local n row
        int gn  = bn + nl;
        int kw0 = (tid & 3) * 32;    // 32 kw per thread
        #pragma unroll
        for (int j = 0; j < 32; j += 4) {
            uint4 h = *reinterpret_cast<const uint4*>(&g_wth[gn * DW + kw0 + j]);
            uint4 l = *reinterpret_cast<const uint4*>(&g_wtl[gn * DW + kw0 + j]);
            unsigned* p = &sw[nl * SROW + (kw0 + j) * 2];
            p[0] = h.x; p[1] = l.x; p[2] = h.y; p[3] = l.y;
            p[4] = h.z; p[5] = l.z; p[6] = h.w; p[7] = l.w;
        }
    }

    int row0 = bm + wid * 16 + grp;       // < NPAD always (padded arrays)
    int row1 = row0 + 8;
    const unsigned* xh0 = &g_xh[row0 * DW];
    const unsigned* xh1 = &g_xh[row1 * DW];
    const unsigned* xl0 = &g_xl[row0 * DW];
    const unsigned* xl1 = &g_xl[row1 * DW];
    __syncthreads();

    float acc[8][4];
    #pragma unroll
    for (int nb = 0; nb < 8; nb++)
        #pragma unroll
        for (int j = 0; j < 4; j++) acc[nb][j] = 0.f;

    unsigned ah[2][4], al[2][4];
    // preload ks = 0
    ah[0][0] = xh0[ctg];     ah[0][1] = xh1[ctg];
    ah[0][2] = xh0[ctg + 4]; ah[0][3] = xh1[ctg + 4];
    al[0][0] = xl0[ctg];     al[0][1] = xl1[ctg];
    al[0][2] = xl0[ctg + 4]; al[0][3] = xl1[ctg + 4];

    #pragma unroll
    for (int ks = 0; ks < 16; ks++) {
        int cur = ks & 1, nxt = cur ^ 1;
        if (ks < 15) {   // prefetch next A fragments while mma runs
            int kwg = (ks + 1) * 8 + ctg;
            ah[nxt][0] = xh0[kwg];     ah[nxt][1] = xh1[kwg];
            ah[nxt][2] = xh0[kwg + 4]; ah[nxt][3] = xh1[kwg + 4];
            al[nxt][0] = xl0[kwg];     al[nxt][1] = xl1[kwg];
            al[nxt][2] = xl0[kwg + 4]; al[nxt][3] = xl1[kwg + 4];
        }
        int kb = (ks * 8 + ctg) * 2;
        #pragma unroll
        for (int nb = 0; nb < 8; nb++) {
            const unsigned* bp = &sw[(nb * 8 + grp) * SROW + kb];
            uint2 b0 = *reinterpret_cast<const uint2*>(bp);       // (bh0, bl0)
            uint2 b1 = *reinterpret_cast<const uint2*>(bp + 8);   // (bh1, bl1)
            float* d = acc[nb];
            asm volatile(
                "mma.sync.aligned.m16n8k16.row.col.f32.bf16.bf16.f32 "
                "{%0,%1,%2,%3}, {%4,%5,%6,%7}, {%8,%9}, {%0,%1,%2,%3};"
                : "+f"(d[0]), "+f"(d[1]), "+f"(d[2]), "+f"(d[3])
                : "r"(ah[cur][0]), "r"(ah[cur][1]), "r"(ah[cur][2]), "r"(ah[cur][3]),
                  "r"(b0.x), "r"(b1.x));
            asm volatile(
                "mma.sync.aligned.m16n8k16.row.col.f32.bf16.bf16.f32 "
                "{%0,%1,%2,%3}, {%4,%5,%6,%7}, {%8,%9}, {%0,%1,%2,%3};"
                : "+f"(d[0]), "+f"(d[1]), "+f"(d[2]), "+f"(d[3])
                : "r"(al[cur][0]), "r"(al[cur][1]), "r"(al[cur][2]), "r"(al[cur][3]),
                  "r"(b0.x), "r"(b1.x));
            asm volatile(
                "mma.sync.aligned.m16n8k16.row.col.f32.bf16.bf16.f32 "
                "{%0,%1,%2,%3}, {%4,%5,%6,%7}, {%8,%9}, {%0,%1,%2,%3};"
                : "+f"(d[0]), "+f"(d[1]), "+f"(d[2]), "+f"(d[3])
                : "r"(ah[cur][0]), "r"(ah[cur][1]), "r"(ah[cur][2]), "r"(ah[cur][3]),
                  "r"(b0.y), "r"(b1.y));
        }
    }

    // ---- epilogue: fp16 convert + store (no dinv; folded into agg) ----
    bool v0 = row0 < N_NODES, v1 = row1 < N_NODES;
    #pragma unroll
    for (int nb = 0; nb < 8; nb++) {
        int n = bn + nb * 8 + 2 * ctg;
        if (v0) {
            __half2 h = __floats2half2_rn(acc[nb][0], acc[nb][1]);
            *reinterpret_cast<__half2*>(&g_zh[row0 * D + n]) = h;
        }
        if (v1) {
            __half2 h = __floats2half2_rn(acc[nb][2], acc[nb][3]);
            *reinterpret_cast<__half2*>(&g_zh[row1 * D + n]) = h;
        }
    }
}

// ============================ aggregation ==================================
// out[i] = dinv_i * ( sum_j dinv_j * z_j + dinv_i * z_i ),  z = xW (fp16)
__global__ __launch_bounds__(128) void agg_kernel(float* __restrict__ out) {
    __shared__ unsigned words[USED_WORDS];
    __shared__ int   list[CAP];
    __shared__ float dlist[CAP];
    __shared__ int   s_count;
    int i = blockIdx.x;
    int t = threadIdx.x;
    if (t == 0) s_count = 0;
    const unsigned* row = &g_bits[i * ROW_WORDS];
    for (int w = t; w < USED_WORDS; w += 128) words[w] = row[w];
    __syncthreads();

    for (int w = t; w < USED_WORDS; w += 128) {
        unsigned m = words[w];
        int n = __popc(m);
        if (n) {
            int base = atomicAdd(&s_count, n);
            while (m) {
                int b = __ffs(m) - 1;
                m &= m - 1;
                if (base < CAP) list[base] = (w << 5) + b;
                base++;
            }
        }
    }
    __syncthreads();
    int c = s_count;
    for (int k = t; k < c && k < CAP; k += 128) dlist[k] = g_dinv[list[k]];
    __syncthreads();

    const __half2* Z = reinterpret_cast<const __half2*>(g_zh);
    float dvi = g_dinv[i];
    float2 self = __half22float2(Z[i * (D / 2) + t]);
    float accx = dvi * self.x, accy = dvi * self.y;

    if (c <= CAP) {
        int k = 0;
        for (; k + 8 <= c; k += 8) {
            float2 a0 = __half22float2(Z[list[k+0] * (D/2) + t]);
            float2 a1 = __half22float2(Z[list[k+1] * (D/2) + t]);
            float2 a2 = __half22float2(Z[list[k+2] * (D/2) + t]);
            float2 a3 = __half22float2(Z[list[k+3] * (D/2) + t]);
            float2 a4 = __half22float2(Z[list[k+4] * (D/2) + t]);
            float2 a5 = __half22float2(Z[list[k+5] * (D/2) + t]);
            float2 a6 = __half22float2(Z[list[k+6] * (D/2) + t]);
            float2 a7 = __half22float2(Z[list[k+7] * (D/2) + t]);
            float d0 = dlist[k+0], d1 = dlist[k+1], d2 = dlist[k+2], d3 = dlist[k+3];
            float d4 = dlist[k+4], d5 = dlist[k+5], d6 = dlist[k+6], d7 = dlist[k+7];
            accx = fmaf(d0, a0.x, accx); accy = fmaf(d0, a0.y, accy);
            accx = fmaf(d1, a1.x, accx); accy = fmaf(d1, a1.y, accy);
            accx = fmaf(d2, a2.x, accx); accy = fmaf(d2, a2.y, accy);
            accx = fmaf(d3, a3.x, accx); accy = fmaf(d3, a3.y, accy);
            accx = fmaf(d4, a4.x, accx); accy = fmaf(d4, a4.y, accy);
            accx = fmaf(d5, a5.x, accx); accy = fmaf(d5, a5.y, accy);
            accx = fmaf(d6, a6.x, accx); accy = fmaf(d6, a6.y, accy);
            accx = fmaf(d7, a7.x, accx); accy = fmaf(d7, a7.y, accy);
        }
        for (; k < c; k++) {
            float2 a = __half22float2(Z[list[k] * (D/2) + t]);
            float dj = dlist[k];
            accx = fmaf(dj, a.x, accx); accy = fmaf(dj, a.y, accy);
        }
    } else {
        #pragma unroll 1
        for (int wi = 0; wi < USED_WORDS; wi++) {
            unsigned w = words[wi];
            while (w) {
                int b = __ffs(w) - 1;
                w &= w - 1;
                int j = (wi << 5) + b;
                float dj = g_dinv[j];
                float2 a = __half22float2(Z[j * (D/2) + t]);
                accx = fmaf(dj, a.x, accx); accy = fmaf(dj, a.y, accy);
            }
        }
    }
    *reinterpret_cast<float2*>(&out[i * D + 2 * t]) =
        make_float2(accx * dvi, accy * dvi);
}

// ---------------------------------------------------------------------------
extern "C" void kernel_launch(void* const* d_in, const int* in_sizes, int n_in,
                              void* d_out, int out_size) {
    const float* x  = nullptr;
    const int*   ei = nullptr;
    const float* w  = nullptr;
    for (int i = 0; i < n_in; i++) {
        if      (in_sizes[i] == N_NODES * D)   x  = (const float*)d_in[i];
        else if (in_sizes[i] == 2 * E_EDGES)   ei = (const int*)d_in[i];
        else if (in_sizes[i] == D * D)         w  = (const float*)d_in[i];
    }
    float* out = (float*)d_out;
    (void)out_size;

    int smem = 64 * SROW * 4;
    cudaFuncSetAttribute(gemm_mma_kernel,
                         cudaFuncAttributeMaxDynamicSharedMemorySize, smem);

    // Order chosen so the GEMM sits in ncu's captured slot (#4).
    split_x_kernel<<<(NPAD * DW + 255) / 256, 256>>>(x);
    split_w_kernel<<<(D * DW + 255) / 256, 256>>>(w);
    zero_bits_kernel<<<2048, 256>>>();
    gemm_mma_kernel<<<dim3(D / 64, NPAD / 128), 256, smem>>>();   // (4, 79)
    edge_kernel<<<(E_EDGES + 255) / 256, 256>>>(ei);
    degree_kernel<<<(N_NODES * 32 + 255) / 256, 256>>>();
    agg_kernel<<<N_NODES, 128>>>(out);
}